// round 1
// baseline (speedup 1.0000x reference)
#include <cuda_runtime.h>

#define CONST_NO 10000
#define PADV 0

constexpr int GG = 8;      // goals per state
constexpr int SS = 64;     // states per batch
constexpr int KF = 64;     // fact top-k
constexpr int KR = 32;     // rule top-k
constexpr int MAXSTATES = 512;
constexpr int NPREDS = 52;     // predicate ids 1..50 (+pad)
constexpr int HIST_BLK = 256;  // facts per histogram/scatter block
constexpr int NB_MAX = 1024;
constexpr int MAXF = 200704;
constexpr int MATCH_THREADS = 512;

__device__ int g_hist[NPREDS * NB_MAX];   // [pred][block] counts -> exclusive offsets
__device__ int g_bucketCount[NPREDS];
__device__ int g_bucketStart[NPREDS];
__device__ int g_sorted[MAXF];            // fact indices grouped by pred, index-sorted
__device__ int g_matchF[MAXSTATES * KF];
__device__ int g_matchR[MAXSTATES * KR];
__device__ int g_nf[MAXSTATES];
__device__ int g_nr[MAXSTATES];

// ---------------- K1: per-block predicate histogram ----------------
__global__ __launch_bounds__(HIST_BLK) void k_hist(const int* __restrict__ facts, int F, int nB) {
    __shared__ int sh[NPREDS];
    int t = threadIdx.x;
    if (t < NPREDS) sh[t] = 0;
    __syncthreads();
    int i = blockIdx.x * HIST_BLK + t;
    if (i < F) {
        int p = facts[3 * i];
        if (p >= 0 && p < NPREDS) atomicAdd(&sh[p], 1);
    }
    __syncthreads();
    if (t < NPREDS) g_hist[t * nB + blockIdx.x] = sh[t];
}

// ---------------- K2: per-predicate exclusive scan over blocks ----------------
__global__ __launch_bounds__(32) void k_scan(int nB) {
    int p = blockIdx.x;
    int lane = threadIdx.x;
    int run = 0;
    for (int base = 0; base < nB; base += 32) {
        int i = base + lane;
        int v = (i < nB) ? g_hist[p * nB + i] : 0;
        int inc = v;
        #pragma unroll
        for (int o = 1; o < 32; o <<= 1) {
            int n = __shfl_up_sync(0xffffffffu, inc, o);
            if (lane >= o) inc += n;
        }
        if (i < nB) g_hist[p * nB + i] = run + inc - v;
        run += __shfl_sync(0xffffffffu, inc, 31);
    }
    if (lane == 0) g_bucketCount[p] = run;
}

// ---------------- K3: bucket starts (scan over 52 predicates) ----------------
__global__ __launch_bounds__(64) void k_starts() {
    __shared__ int sh[64];
    int t = threadIdx.x;
    int c = (t < NPREDS) ? g_bucketCount[t] : 0;
    sh[t] = c;
    __syncthreads();
    #pragma unroll
    for (int o = 1; o < 64; o <<= 1) {
        int v = (t >= o) ? sh[t - o] : 0;
        __syncthreads();
        sh[t] += v;
        __syncthreads();
    }
    if (t < NPREDS) g_bucketStart[t] = sh[t] - c;
}

// ---------------- K4: stable scatter into buckets ----------------
__global__ __launch_bounds__(HIST_BLK) void k_scatter(const int* __restrict__ facts, int F, int nB) {
    __shared__ int warpHist[HIST_BLK / 32][NPREDS];
    int t = threadIdx.x, w = t >> 5, lane = t & 31;
    for (int j = t; j < (HIST_BLK / 32) * NPREDS; j += HIST_BLK)
        ((int*)warpHist)[j] = 0;
    __syncthreads();
    int i = blockIdx.x * HIST_BLK + t;
    int p = -1;
    if (i < F) {
        p = facts[3 * i];
        if (p < 0 || p >= NPREDS) p = -1;
    }
    unsigned mask = __match_any_sync(0xffffffffu, p);
    int rank = __popc(mask & ((1u << lane) - 1));
    int leader = __ffs(mask) - 1;
    if (p >= 0 && lane == leader) warpHist[w][p] = __popc(mask);
    __syncthreads();
    if (p >= 0) {
        int base = 0;
        #pragma unroll
        for (int ww = 0; ww < HIST_BLK / 32; ww++)
            if (ww < w) base += warpHist[ww][p];
        int pos = g_bucketStart[p] + g_hist[p * nB + blockIdx.x] + base + rank;
        g_sorted[pos] = i;
    }
}

// ---------------- K5: per-state match (ordered first-K collection) ----------------
__global__ __launch_bounds__(MATCH_THREADS) void k_match(const int* __restrict__ goals,
                                                         const int* __restrict__ facts,
                                                         const int* __restrict__ heads, int R) {
    constexpr int NW = MATCH_THREADS / 32;
    int state = blockIdx.x;
    const int* pg = goals + state * GG * 3;
    int qp = pg[0], qa0 = pg[1], qa1 = pg[2];
    int t = threadIdx.x, w = t >> 5, lane = t & 31;
    __shared__ int warpCnt[NW];
    int nf = 0, nr = 0;
    bool active = (qp != PADV);
    if (active) {
        bool v0 = qa0 > CONST_NO, v1 = qa1 > CONST_NO;
        int start = 0, cnt = 0;
        if (qp >= 0 && qp < NPREDS) { start = g_bucketStart[qp]; cnt = g_bucketCount[qp]; }
        int collected = 0;
        for (int base = 0; base < cnt; base += MATCH_THREADS) {
            int i = base + t;
            bool m = false;
            int fi = 0;
            if (i < cnt) {
                fi = g_sorted[start + i];
                int a0 = __ldg(&facts[3 * fi + 1]);
                int a1 = __ldg(&facts[3 * fi + 2]);
                m = (v0 || qa0 == a0) && (v1 || qa1 == a1);
            }
            unsigned bal = __ballot_sync(0xffffffffu, m);
            if (lane == 0) warpCnt[w] = __popc(bal);
            __syncthreads();
            int wbase = 0, total = 0;
            #pragma unroll
            for (int ww = 0; ww < NW; ww++) {
                int c = warpCnt[ww];
                if (ww < w) wbase += c;
                total += c;
            }
            int pos = collected + wbase + __popc(bal & ((1u << lane) - 1));
            if (m && pos < KF) g_matchF[state * KF + pos] = fi;
            collected += total;
            __syncthreads();
            if (collected >= KF) break;
        }
        nf = min(collected, KF);

        collected = 0;
        for (int base = 0; base < R; base += MATCH_THREADS) {
            int i = base + t;
            bool m = false;
            if (i < R) {
                int hp = heads[3 * i], h1 = heads[3 * i + 1], h2 = heads[3 * i + 2];
                m = (hp == qp)
                    && (h1 > CONST_NO || v0 || qa0 == h1)
                    && (h2 > CONST_NO || v1 || qa1 == h2);
            }
            unsigned bal = __ballot_sync(0xffffffffu, m);
            if (lane == 0) warpCnt[w] = __popc(bal);
            __syncthreads();
            int wbase = 0, total = 0;
            #pragma unroll
            for (int ww = 0; ww < NW; ww++) {
                int c = warpCnt[ww];
                if (ww < w) wbase += c;
                total += c;
            }
            int pos = collected + wbase + __popc(bal & ((1u << lane) - 1));
            if (m && pos < KR) g_matchR[state * KR + pos] = i;
            collected += total;
            __syncthreads();
            if (collected >= KR) break;
        }
        nr = min(collected, KR);
    }
    if (t == 0) {
        g_nf[state] = nf;
        g_nr[state] = nr;
    }
}

// ---------------- K6: per-batch select + construct winners ----------------
__global__ __launch_bounds__(64) void k_select(const int* __restrict__ goals,
                                               const float* __restrict__ stateScores,
                                               const int* __restrict__ facts,
                                               const float* __restrict__ factScores,
                                               const int* __restrict__ heads,
                                               const int* __restrict__ bodies,
                                               const int* __restrict__ ruleLens,
                                               const float* __restrict__ ruleScores,
                                               float* __restrict__ out, int numStates) {
    int b = blockIdx.x;
    int t = threadIdx.x;  // output slot j in [0, SS)
    __shared__ int cnts[SS];
    __shared__ int cum[SS + 1];
    if (t < SS) cnts[t] = g_nf[b * SS + t] + g_nr[b * SS + t];
    __syncthreads();
    if (t == 0) {
        int a = 0;
        for (int s = 0; s < SS; s++) { cum[s] = a; a += cnts[s]; }
        cum[SS] = a;
    }
    __syncthreads();

    int goalsCount = numStates * GG * 3;
    int j = t;
    int outBase = (b * SS + j) * (GG * 3);
    int total = cum[SS];
    if (j < total) {
        int s = 0;
        while (s < SS - 1 && cum[s + 1] <= j) s++;
        int off = j - cum[s];
        int state = b * SS + s;
        int nf = g_nf[state];
        const int* pg = goals + state * GG * 3;
        int qa0 = pg[1], qa1 = pg[2];
        float ss = stateScores[state];
        int og[GG * 3];
        float score;
        if (off < nf) {
            // fact expansion
            int fi = g_matchF[state * KF + off];
            int b0 = facts[3 * fi + 1], b1 = facts[3 * fi + 2];
            bool v0 = qa0 > CONST_NO, v1 = qa1 > CONST_NO;
            #pragma unroll
            for (int e = 0; e < GG * 3; e++) {
                int x = (e < 3) ? PADV : pg[e];  // goal 0 zeroed
                if (v0 && x == qa0) x = b0;
                if (v1 && x == qa1) x = b1;
                og[e] = x;
            }
            score = ss * factScores[fi];
        } else {
            // rule expansion
            int ri = g_matchR[state * KR + (off - nf)];
            int h1 = heads[3 * ri + 1], h2 = heads[3 * ri + 2];
            bool v0 = h1 > CONST_NO, v1 = h2 > CONST_NO;
            int len = ruleLens[ri];
            #pragma unroll
            for (int jg = 0; jg < 3; jg++) {
                #pragma unroll
                for (int c = 0; c < 3; c++) {
                    int x = bodies[ri * 9 + jg * 3 + c];
                    if (v0 && x == h1) x = qa0;
                    if (v1 && x == h2) x = qa1;
                    if (jg >= len) x = PADV;
                    og[jg * 3 + c] = x;
                }
            }
            #pragma unroll
            for (int jg = 3; jg < GG; jg++)
                #pragma unroll
                for (int c = 0; c < 3; c++)
                    og[jg * 3 + c] = pg[(jg - 2) * 3 + c];  // remaining goals 1..5
            score = ss * ruleScores[ri];
        }
        #pragma unroll
        for (int e = 0; e < GG * 3; e++) out[outBase + e] = (float)og[e];
        out[goalsCount + b * SS + j] = score;
    } else {
        #pragma unroll
        for (int e = 0; e < GG * 3; e++) out[outBase + e] = 0.0f;
        out[goalsCount + b * SS + j] = 0.0f;
    }
}

extern "C" void kernel_launch(void* const* d_in, const int* in_sizes, int n_in,
                              void* d_out, int out_size) {
    const int* goals = (const int*)d_in[0];        // (B,S,G,3) int32
    const float* stateScores = (const float*)d_in[1];  // (B,S)
    const int* facts = (const int*)d_in[2];        // (F,3)
    const float* factScores = (const float*)d_in[3];
    const int* heads = (const int*)d_in[4];        // (R,3)
    const int* bodies = (const int*)d_in[5];       // (R,3,3)
    const int* ruleLens = (const int*)d_in[6];
    const float* ruleScores = (const float*)d_in[7];

    int F = in_sizes[2] / 3;
    int R = in_sizes[4] / 3;
    int numStates = in_sizes[1];       // B*S
    int numBatches = numStates / SS;   // B
    int nB = (F + HIST_BLK - 1) / HIST_BLK;

    k_hist<<<nB, HIST_BLK>>>(facts, F, nB);
    k_scan<<<NPREDS, 32>>>(nB);
    k_starts<<<1, 64>>>();
    k_scatter<<<nB, HIST_BLK>>>(facts, F, nB);
    k_match<<<numStates, MATCH_THREADS>>>(goals, facts, heads, R);
    k_select<<<numBatches, 64>>>(goals, stateScores, facts, factScores, heads,
                                 bodies, ruleLens, ruleScores, (float*)d_out, numStates);
}